// round 1
// baseline (speedup 1.0000x reference)
#include <cuda_runtime.h>
#include <math.h>
#include <stdint.h>

#define Bn 1024
#define Tn 64
#define Dn 512
#define Hn 512
#define Cn 96
#define Sn 21
#define DCn (Dn + Cn)   // 608

// ---------------- scratch (device globals; no runtime allocation) ----------------
__device__ float g_Hp[(size_t)Bn * Tn * Hn];     // 128 MB: precomputed i2h(batch_H)
__device__ float g_h[Bn * Hn];
__device__ float g_c[Bn * Hn];
__device__ float g_ph[Bn * Hn];
__device__ float g_ctx[Bn * Dn];
__device__ float g_gates[Bn * 4 * Hn];
__device__ float g_hs[(size_t)Bn * Sn * Hn];     // 43 MB

// ---------------- helpers ----------------
__device__ __forceinline__ float tanh_fast(float x) {
    float y;
    asm("tanh.approx.f32 %0, %1;" : "=f"(y) : "f"(x));
    return y;
}
__device__ __forceinline__ float sigmoidf(float x) {
    return 1.0f / (1.0f + expf(-x));
}

// ---------------- init h, c = 0 ----------------
__global__ void init_state_kernel() {
    int i = blockIdx.x * blockDim.x + threadIdx.x;
    if (i < Bn * Hn) { g_h[i] = 0.0f; g_c[i] = 0.0f; }
}

// ---------------- generic SGEMM: C[m,n] = sum_k A[m,k]*B[n,k] (+bias[n]) (+=C) ----
// A row-major [M x lda], B row-major [N x ldb] (K contiguous in both), C [M x ldc].
// BM=128, BN=64, BK=16, TM=8, TN=4, 256 threads.
template <bool ACC, bool BIAS>
__global__ __launch_bounds__(256)
void sgemm_nt(const float* __restrict__ A, int lda,
              const float* __restrict__ Bm, int ldb,
              const float* __restrict__ bias,
              float* __restrict__ C, int ldc,
              int M, int N, int K)
{
    constexpr int BM = 128, BN = 64, BK = 16, TM = 8, TN = 4;
    __shared__ float As[BK][BM];
    __shared__ float Bs[BK][BN];

    const int tid = threadIdx.x;
    const int tx = tid % (BN / TN);   // 0..15 (n)
    const int ty = tid / (BN / TN);   // 0..15 (m)
    const int m0 = blockIdx.y * BM;
    const int n0 = blockIdx.x * BN;

    float acc[TM][TN];
#pragma unroll
    for (int i = 0; i < TM; i++)
#pragma unroll
        for (int j = 0; j < TN; j++) acc[i][j] = 0.0f;

    for (int k0 = 0; k0 < K; k0 += BK) {
        // load A tile: 128x16 = 512 float4, 2 per thread
#pragma unroll
        for (int v = 0; v < 2; v++) {
            int f = tid + v * 256;          // 0..511
            int r = f >> 2;                 // 0..127
            int c4 = (f & 3) << 2;          // 0,4,8,12
            float4 val = make_float4(0.f, 0.f, 0.f, 0.f);
            int gr = m0 + r;
            if (gr < M)
                val = *reinterpret_cast<const float4*>(&A[(size_t)gr * lda + k0 + c4]);
            As[c4 + 0][r] = val.x;
            As[c4 + 1][r] = val.y;
            As[c4 + 2][r] = val.z;
            As[c4 + 3][r] = val.w;
        }
        // load B tile: 64x16 = 256 float4, 1 per thread
        {
            int f = tid;
            int r = f >> 2;                 // 0..63
            int c4 = (f & 3) << 2;
            float4 val = make_float4(0.f, 0.f, 0.f, 0.f);
            int gr = n0 + r;
            if (gr < N)
                val = *reinterpret_cast<const float4*>(&Bm[(size_t)gr * ldb + k0 + c4]);
            Bs[c4 + 0][r] = val.x;
            Bs[c4 + 1][r] = val.y;
            Bs[c4 + 2][r] = val.z;
            Bs[c4 + 3][r] = val.w;
        }
        __syncthreads();

#pragma unroll
        for (int kk = 0; kk < BK; kk++) {
            float ra[TM], rb[TN];
#pragma unroll
            for (int i = 0; i < TM; i++) ra[i] = As[kk][ty * TM + i];
#pragma unroll
            for (int j = 0; j < TN; j++) rb[j] = Bs[kk][tx * TN + j];
#pragma unroll
            for (int i = 0; i < TM; i++)
#pragma unroll
                for (int j = 0; j < TN; j++)
                    acc[i][j] = fmaf(ra[i], rb[j], acc[i][j]);
        }
        __syncthreads();
    }

#pragma unroll
    for (int i = 0; i < TM; i++) {
        int m = m0 + ty * TM + i;
        if (m >= M) continue;
#pragma unroll
        for (int j = 0; j < TN; j++) {
            int n = n0 + tx * TN + j;
            if (n >= N) continue;
            float v = acc[i][j];
            if (BIAS) v += bias[n];
            size_t idx = (size_t)m * ldc + n;
            if (ACC) v += C[idx];
            C[idx] = v;
        }
    }
}

// ---------------- fused attention: score + softmax + context, one block per b ----
__global__ __launch_bounds__(256)
void attn_kernel(const float* __restrict__ batch_H,
                 const float* __restrict__ Ws)
{
    const int b = blockIdx.x;
    __shared__ float ph_s[Hn];
    __shared__ float ws_s[Hn];
    __shared__ float e_s[Tn];
    __shared__ float alpha_s[Tn];

    const int tid = threadIdx.x;
    for (int i = tid; i < Hn; i += 256) {
        ph_s[i] = g_ph[b * Hn + i];
        ws_s[i] = Ws[i];
    }
    __syncthreads();

    const int warp = tid >> 5, lane = tid & 31;
    const float* hp_b = &g_Hp[(size_t)b * Tn * Hn];

    // e[t] = sum_h tanh(Hp[b,t,h] + ph[b,h]) * Ws[h]
    for (int t = warp; t < Tn; t += 8) {
        const float* hp = hp_b + t * Hn;
        float a = 0.0f;
#pragma unroll 4
        for (int h = lane; h < Hn; h += 32)
            a = fmaf(tanh_fast(hp[h] + ph_s[h]), ws_s[h], a);
#pragma unroll
        for (int o = 16; o > 0; o >>= 1)
            a += __shfl_xor_sync(0xffffffffu, a, o);
        if (lane == 0) e_s[t] = a;
    }
    __syncthreads();

    // softmax over T=64 by warp 0 (2 elems per lane)
    if (warp == 0) {
        float e0 = e_s[lane], e1 = e_s[lane + 32];
        float m = fmaxf(e0, e1);
#pragma unroll
        for (int o = 16; o > 0; o >>= 1)
            m = fmaxf(m, __shfl_xor_sync(0xffffffffu, m, o));
        float x0 = expf(e0 - m), x1 = expf(e1 - m);
        float s = x0 + x1;
#pragma unroll
        for (int o = 16; o > 0; o >>= 1)
            s += __shfl_xor_sync(0xffffffffu, s, o);
        float inv = 1.0f / s;
        alpha_s[lane] = x0 * inv;
        alpha_s[lane + 32] = x1 * inv;
    }
    __syncthreads();

    // ctx[b,d] = sum_t alpha[t] * batch_H[b,t,d]  (each thread does d and d+256)
    const float* bhp = &batch_H[(size_t)b * Tn * Dn];
    float a0 = 0.0f, a1 = 0.0f;
#pragma unroll 8
    for (int t = 0; t < Tn; t++) {
        float al = alpha_s[t];
        a0 = fmaf(al, bhp[t * Dn + tid], a0);
        a1 = fmaf(al, bhp[t * Dn + tid + 256], a1);
    }
    g_ctx[b * Dn + tid] = a0;
    g_ctx[b * Dn + tid + 256] = a1;
}

// ---------------- LSTM pointwise + one-hot column gather + biases ----------------
__global__ __launch_bounds__(256)
void lstm_kernel(const float* __restrict__ Wih,
                 const float* __restrict__ bih,
                 const float* __restrict__ bhh,
                 const int* __restrict__ text,
                 int s)
{
    int idx = blockIdx.x * blockDim.x + threadIdx.x;
    if (idx >= Bn * Hn) return;
    int b = idx / Hn, n = idx % Hn;
    int tok = text[b * Sn + s];
    int col = Dn + tok;

    const float* grow = &g_gates[(size_t)b * 4 * Hn];
    float ig = grow[n]          + Wih[(size_t)(n)          * DCn + col] + bih[n]          + bhh[n];
    float fg = grow[Hn + n]     + Wih[(size_t)(Hn + n)     * DCn + col] + bih[Hn + n]     + bhh[Hn + n];
    float gg = grow[2 * Hn + n] + Wih[(size_t)(2 * Hn + n) * DCn + col] + bih[2 * Hn + n] + bhh[2 * Hn + n];
    float og = grow[3 * Hn + n] + Wih[(size_t)(3 * Hn + n) * DCn + col] + bih[3 * Hn + n] + bhh[3 * Hn + n];

    float c_old = g_c[idx];
    float cn = sigmoidf(fg) * c_old + sigmoidf(ig) * tanhf(gg);
    float hn = sigmoidf(og) * tanhf(cn);
    g_c[idx] = cn;
    g_h[idx] = hn;
    g_hs[((size_t)b * Sn + s) * Hn + n] = hn;
}

// ---------------- launch ----------------
extern "C" void kernel_launch(void* const* d_in, const int* in_sizes, int n_in,
                              void* d_out, int out_size)
{
    const float* batch_H = (const float*)d_in[0];
    const int*   text    = (const int*)  d_in[1];
    const float* Wi      = (const float*)d_in[2];
    const float* Wh      = (const float*)d_in[3];
    const float* bh      = (const float*)d_in[4];
    const float* Ws      = (const float*)d_in[5];
    const float* Wih     = (const float*)d_in[6];
    const float* Whh     = (const float*)d_in[7];
    const float* bih     = (const float*)d_in[8];
    const float* bhh     = (const float*)d_in[9];
    const float* Wg      = (const float*)d_in[10];
    const float* bg      = (const float*)d_in[11];
    float* out = (float*)d_out;

    float *Hp, *h, *ph, *ctx, *gates, *hs;
    cudaGetSymbolAddress((void**)&Hp,    g_Hp);
    cudaGetSymbolAddress((void**)&h,     g_h);
    cudaGetSymbolAddress((void**)&ph,    g_ph);
    cudaGetSymbolAddress((void**)&ctx,   g_ctx);
    cudaGetSymbolAddress((void**)&gates, g_gates);
    cudaGetSymbolAddress((void**)&hs,    g_hs);

    // h = c = 0
    init_state_kernel<<<(Bn * Hn + 255) / 256, 256>>>();

    // Hp = batch_H @ Wi^T   [65536 x 512]
    sgemm_nt<false, false><<<dim3(512 / 64, (Bn * Tn) / 128), 256>>>(
        batch_H, Dn, Wi, Dn, nullptr, Hp, Hn, Bn * Tn, Hn, Dn);

    for (int s = 0; s < Sn; s++) {
        // ph = h @ Wh^T + bh   [1024 x 512]
        sgemm_nt<false, true><<<dim3(512 / 64, Bn / 128), 256>>>(
            h, Hn, Wh, Hn, bh, ph, Hn, Bn, Hn, Hn);

        // attention: e -> softmax -> ctx
        attn_kernel<<<Bn, 256>>>(batch_H, Ws);

        // gates = ctx @ Wih[:, :512]^T   [1024 x 2048]
        sgemm_nt<false, false><<<dim3(2048 / 64, Bn / 128), 256>>>(
            ctx, Dn, Wih, DCn, nullptr, gates, 4 * Hn, Bn, 4 * Hn, Dn);
        // gates += h @ Whh^T
        sgemm_nt<true, false><<<dim3(2048 / 64, Bn / 128), 256>>>(
            h, Hn, Whh, Hn, nullptr, gates, 4 * Hn, Bn, 4 * Hn, Hn);

        // LSTM pointwise (adds one-hot Wih column + both biases), writes h,c,hs[s]
        lstm_kernel<<<(Bn * Hn + 255) / 256, 256>>>(Wih, bih, bhh, text, s);
    }

    // probs = hs @ Wg^T + bg   [21504 x 96] -> d_out
    sgemm_nt<false, true><<<dim3((Cn + 63) / 64, (Bn * Sn) / 128), 256>>>(
        hs, Hn, Wg, Hn, bg, out, Cn, Bn * Sn, Cn, Hn);
}

// round 2
// speedup vs baseline: 2.3090x; 2.3090x over previous
#include <cuda_runtime.h>
#include <math.h>
#include <stdint.h>

#define Bn 1024
#define Tn 64
#define Dn 512
#define Hn 512
#define Cn 96
#define Sn 21
#define DCn (Dn + Cn)   // 608
#define XCn (Dn + Hn)   // 1024

// ---------------- scratch (device globals) ----------------
__device__ float g_Hp[(size_t)Bn * Tn * Hn];     // 128 MB
__device__ float g_c[Bn * Hn];
__device__ float g_ph[Bn * Hn];
__device__ float g_xcat[Bn * XCn];               // [ctx | h]
__device__ float g_gates[Bn * 4 * Hn];
__device__ float g_hs[(size_t)Bn * Sn * Hn];
__device__ float g_Wcat[(size_t)4 * Hn * XCn];   // [Wih[:,:512] | Whh]  2048x1024
__device__ float g_ohb[Cn * 4 * Hn];             // Wih[:,512+c] + bih + bhh

// ---------------- helpers ----------------
__device__ __forceinline__ float tanh_fast(float x) {
    float y;
    asm("tanh.approx.f32 %0, %1;" : "=f"(y) : "f"(x));
    return y;
}
__device__ __forceinline__ float sigmoidf(float x) {
    return 1.0f / (1.0f + expf(-x));
}
__device__ __forceinline__ uint32_t f2tf(float x) {
    uint32_t u;
    asm("cvt.rna.tf32.f32 %0, %1;" : "=r"(u) : "f"(x));
    return u;
}

// ---------------- init: zero c and xcat ----------------
__global__ void init_state_kernel() {
    int i = blockIdx.x * blockDim.x + threadIdx.x;
    if (i < Bn * XCn) g_xcat[i] = 0.0f;
    if (i < Bn * Hn)  g_c[i] = 0.0f;
}

// ---------------- prep: Wcat + ohb ----------------
__global__ void build_wcat_kernel(const float* __restrict__ Wih,
                                  const float* __restrict__ Whh) {
    int idx = blockIdx.x * blockDim.x + threadIdx.x;
    if (idx >= 4 * Hn * XCn) return;
    int n = idx >> 10;        // row in [0,2048)
    int k = idx & 1023;       // col in [0,1024)
    float v = (k < Dn) ? Wih[(size_t)n * DCn + k] : Whh[(size_t)n * Hn + (k - Dn)];
    g_Wcat[idx] = v;
}
__global__ void build_ohb_kernel(const float* __restrict__ Wih,
                                 const float* __restrict__ bih,
                                 const float* __restrict__ bhh) {
    int idx = blockIdx.x * blockDim.x + threadIdx.x;
    if (idx >= Cn * 4 * Hn) return;
    int c = idx / (4 * Hn);
    int j = idx % (4 * Hn);
    g_ohb[idx] = Wih[(size_t)j * DCn + Dn + c] + bih[j] + bhh[j];
}

// ---------------- tf32 tensor-core GEMM ----------------
// C[m,n] = sum_k A[m,k]*B[n,k] (+ bias[n]).  Requires M%128==0, N%64==0, K%32==0.
// Block tile 128x64x32, 256 threads (8 warps, 4m x 2n), warp tile 32x32.
template <bool BIAS>
__global__ __launch_bounds__(256)
void gemm_tf32(const float* __restrict__ A, int lda,
               const float* __restrict__ B, int ldb,
               const float* __restrict__ bias,
               float* __restrict__ C, int ldc,
               int M, int N, int K)
{
    __shared__ uint32_t As[128][36];   // pad 36 -> conflict-free frag loads
    __shared__ uint32_t Bs[64][36];

    const int tid = threadIdx.x;
    const int warp = tid >> 5, lane = tid & 31;
    const int g = lane >> 2, tig = lane & 3;
    const int wm = warp >> 1, wn = warp & 1;
    const int m0 = blockIdx.y * 128, n0 = blockIdx.x * 64;

    const float* Aptr = A + (size_t)m0 * lda;
    const float* Bptr = B + (size_t)n0 * ldb;

    float4 pa[4], pb[2];
    float acc[2][4][4];
#pragma unroll
    for (int i = 0; i < 2; i++)
#pragma unroll
        for (int j = 0; j < 4; j++)
#pragma unroll
            for (int l = 0; l < 4; l++) acc[i][j][l] = 0.0f;

    // prefetch tile 0 into registers
#pragma unroll
    for (int v = 0; v < 4; v++) {
        int f = tid + v * 256;
        pa[v] = *reinterpret_cast<const float4*>(Aptr + (size_t)(f >> 3) * lda + ((f & 7) << 2));
    }
#pragma unroll
    for (int v = 0; v < 2; v++) {
        int f = tid + v * 256;
        pb[v] = *reinterpret_cast<const float4*>(Bptr + (size_t)(f >> 3) * ldb + ((f & 7) << 2));
    }

    for (int k0 = 0; k0 < K; k0 += 32) {
        // store prefetched tile (tf32-rounded) into smem
#pragma unroll
        for (int v = 0; v < 4; v++) {
            int f = tid + v * 256; int r = f >> 3, c = (f & 7) << 2;
            uint4 q = make_uint4(f2tf(pa[v].x), f2tf(pa[v].y), f2tf(pa[v].z), f2tf(pa[v].w));
            *reinterpret_cast<uint4*>(&As[r][c]) = q;
        }
#pragma unroll
        for (int v = 0; v < 2; v++) {
            int f = tid + v * 256; int r = f >> 3, c = (f & 7) << 2;
            uint4 q = make_uint4(f2tf(pb[v].x), f2tf(pb[v].y), f2tf(pb[v].z), f2tf(pb[v].w));
            *reinterpret_cast<uint4*>(&Bs[r][c]) = q;
        }
        __syncthreads();

        // prefetch next tile
        if (k0 + 32 < K) {
            const float* An = Aptr + k0 + 32;
            const float* Bnp = Bptr + k0 + 32;
#pragma unroll
            for (int v = 0; v < 4; v++) {
                int f = tid + v * 256;
                pa[v] = *reinterpret_cast<const float4*>(An + (size_t)(f >> 3) * lda + ((f & 7) << 2));
            }
#pragma unroll
            for (int v = 0; v < 2; v++) {
                int f = tid + v * 256;
                pb[v] = *reinterpret_cast<const float4*>(Bnp + (size_t)(f >> 3) * ldb + ((f & 7) << 2));
            }
        }

        // compute on smem tile
#pragma unroll
        for (int ks = 0; ks < 4; ks++) {
            const int kk = ks * 8;
            uint32_t af[2][4], bf[4][2];
#pragma unroll
            for (int mt = 0; mt < 2; mt++) {
                int mb = wm * 32 + mt * 16;
                af[mt][0] = As[mb + g][kk + tig];
                af[mt][1] = As[mb + g + 8][kk + tig];
                af[mt][2] = As[mb + g][kk + tig + 4];
                af[mt][3] = As[mb + g + 8][kk + tig + 4];
            }
#pragma unroll
            for (int nt = 0; nt < 4; nt++) {
                int nb = wn * 32 + nt * 8 + g;
                bf[nt][0] = Bs[nb][kk + tig];
                bf[nt][1] = Bs[nb][kk + tig + 4];
            }
#pragma unroll
            for (int mt = 0; mt < 2; mt++)
#pragma unroll
                for (int nt = 0; nt < 4; nt++)
                    asm volatile(
                        "mma.sync.aligned.m16n8k8.row.col.f32.tf32.tf32.f32 "
                        "{%0,%1,%2,%3}, {%4,%5,%6,%7}, {%8,%9}, {%0,%1,%2,%3};"
                        : "+f"(acc[mt][nt][0]), "+f"(acc[mt][nt][1]),
                          "+f"(acc[mt][nt][2]), "+f"(acc[mt][nt][3])
                        : "r"(af[mt][0]), "r"(af[mt][1]), "r"(af[mt][2]), "r"(af[mt][3]),
                          "r"(bf[nt][0]), "r"(bf[nt][1]));
        }
        __syncthreads();
    }

    // epilogue
#pragma unroll
    for (int mt = 0; mt < 2; mt++) {
        int row = m0 + wm * 32 + mt * 16 + g;
#pragma unroll
        for (int nt = 0; nt < 4; nt++) {
            int col = n0 + wn * 32 + nt * 8 + 2 * tig;
            float b0 = 0.f, b1 = 0.f;
            if (BIAS) { b0 = bias[col]; b1 = bias[col + 1]; }
            float2 v0 = make_float2(acc[mt][nt][0] + b0, acc[mt][nt][1] + b1);
            float2 v1 = make_float2(acc[mt][nt][2] + b0, acc[mt][nt][3] + b1);
            *reinterpret_cast<float2*>(&C[(size_t)row * ldc + col]) = v0;
            *reinterpret_cast<float2*>(&C[(size_t)(row + 8) * ldc + col]) = v1;
        }
    }
}

// ---------------- fp32 SGEMM (generator only: ragged N=96) ----------------
template <bool ACC, bool BIAS>
__global__ __launch_bounds__(256)
void sgemm_nt(const float* __restrict__ A, int lda,
              const float* __restrict__ Bm, int ldb,
              const float* __restrict__ bias,
              float* __restrict__ C, int ldc,
              int M, int N, int K)
{
    constexpr int BM = 128, BN = 64, BK = 16, TM = 8, TN = 4;
    __shared__ float As[BK][BM];
    __shared__ float Bs[BK][BN];

    const int tid = threadIdx.x;
    const int tx = tid % (BN / TN);
    const int ty = tid / (BN / TN);
    const int m0 = blockIdx.y * BM;
    const int n0 = blockIdx.x * BN;

    float acc[TM][TN];
#pragma unroll
    for (int i = 0; i < TM; i++)
#pragma unroll
        for (int j = 0; j < TN; j++) acc[i][j] = 0.0f;

    for (int k0 = 0; k0 < K; k0 += BK) {
#pragma unroll
        for (int v = 0; v < 2; v++) {
            int f = tid + v * 256;
            int r = f >> 2;
            int c4 = (f & 3) << 2;
            float4 val = make_float4(0.f, 0.f, 0.f, 0.f);
            int gr = m0 + r;
            if (gr < M)
                val = *reinterpret_cast<const float4*>(&A[(size_t)gr * lda + k0 + c4]);
            As[c4 + 0][r] = val.x; As[c4 + 1][r] = val.y;
            As[c4 + 2][r] = val.z; As[c4 + 3][r] = val.w;
        }
        {
            int f = tid;
            int r = f >> 2;
            int c4 = (f & 3) << 2;
            float4 val = make_float4(0.f, 0.f, 0.f, 0.f);
            int gr = n0 + r;
            if (gr < N)
                val = *reinterpret_cast<const float4*>(&Bm[(size_t)gr * ldb + k0 + c4]);
            Bs[c4 + 0][r] = val.x; Bs[c4 + 1][r] = val.y;
            Bs[c4 + 2][r] = val.z; Bs[c4 + 3][r] = val.w;
        }
        __syncthreads();
#pragma unroll
        for (int kk = 0; kk < BK; kk++) {
            float ra[TM], rb[TN];
#pragma unroll
            for (int i = 0; i < TM; i++) ra[i] = As[kk][ty * TM + i];
#pragma unroll
            for (int j = 0; j < TN; j++) rb[j] = Bs[kk][tx * TN + j];
#pragma unroll
            for (int i = 0; i < TM; i++)
#pragma unroll
                for (int j = 0; j < TN; j++)
                    acc[i][j] = fmaf(ra[i], rb[j], acc[i][j]);
        }
        __syncthreads();
    }
#pragma unroll
    for (int i = 0; i < TM; i++) {
        int m = m0 + ty * TM + i;
        if (m >= M) continue;
#pragma unroll
        for (int j = 0; j < TN; j++) {
            int n = n0 + tx * TN + j;
            if (n >= N) continue;
            float v = acc[i][j];
            if (BIAS) v += bias[n];
            size_t idx = (size_t)m * ldc + n;
            if (ACC) v += C[idx];
            C[idx] = v;
        }
    }
}

// ---------------- fused attention ----------------
__global__ __launch_bounds__(256)
void attn_kernel(const float* __restrict__ batch_H,
                 const float* __restrict__ Ws)
{
    const int b = blockIdx.x;
    __shared__ float ph_s[Hn];
    __shared__ float ws_s[Hn];
    __shared__ float e_s[Tn];
    __shared__ float alpha_s[Tn];

    const int tid = threadIdx.x;
    for (int i = tid; i < Hn; i += 256) {
        ph_s[i] = g_ph[b * Hn + i];
        ws_s[i] = Ws[i];
    }
    __syncthreads();

    const int warp = tid >> 5, lane = tid & 31;
    const float* hp_b = &g_Hp[(size_t)b * Tn * Hn];

    for (int t = warp; t < Tn; t += 8) {
        const float* hp = hp_b + t * Hn;
        float a = 0.0f;
#pragma unroll 4
        for (int h = lane; h < Hn; h += 32)
            a = fmaf(tanh_fast(hp[h] + ph_s[h]), ws_s[h], a);
#pragma unroll
        for (int o = 16; o > 0; o >>= 1)
            a += __shfl_xor_sync(0xffffffffu, a, o);
        if (lane == 0) e_s[t] = a;
    }
    __syncthreads();

    if (warp == 0) {
        float e0 = e_s[lane], e1 = e_s[lane + 32];
        float m = fmaxf(e0, e1);
#pragma unroll
        for (int o = 16; o > 0; o >>= 1)
            m = fmaxf(m, __shfl_xor_sync(0xffffffffu, m, o));
        float x0 = expf(e0 - m), x1 = expf(e1 - m);
        float s = x0 + x1;
#pragma unroll
        for (int o = 16; o > 0; o >>= 1)
            s += __shfl_xor_sync(0xffffffffu, s, o);
        float inv = 1.0f / s;
        alpha_s[lane] = x0 * inv;
        alpha_s[lane + 32] = x1 * inv;
    }
    __syncthreads();

    const float* bhp = &batch_H[(size_t)b * Tn * Dn];
    float a0 = 0.0f, a1 = 0.0f;
#pragma unroll 8
    for (int t = 0; t < Tn; t++) {
        float al = alpha_s[t];
        a0 = fmaf(al, bhp[t * Dn + tid], a0);
        a1 = fmaf(al, bhp[t * Dn + tid + 256], a1);
    }
    g_xcat[b * XCn + tid] = a0;
    g_xcat[b * XCn + tid + 256] = a1;
}

// ---------------- LSTM pointwise ----------------
__global__ __launch_bounds__(256)
void lstm_kernel(const int* __restrict__ text, int s)
{
    int idx = blockIdx.x * blockDim.x + threadIdx.x;
    if (idx >= Bn * Hn) return;
    int b = idx / Hn, n = idx % Hn;
    int tok = text[b * Sn + s];

    const float* grow = &g_gates[(size_t)b * 4 * Hn];
    const float* orow = &g_ohb[(size_t)tok * 4 * Hn];
    float ig = grow[n]          + orow[n];
    float fg = grow[Hn + n]     + orow[Hn + n];
    float gg = grow[2 * Hn + n] + orow[2 * Hn + n];
    float og = grow[3 * Hn + n] + orow[3 * Hn + n];

    float c_old = g_c[idx];
    float cn = sigmoidf(fg) * c_old + sigmoidf(ig) * tanhf(gg);
    float hn = sigmoidf(og) * tanhf(cn);
    g_c[idx] = cn;
    g_xcat[b * XCn + Dn + n] = hn;
    g_hs[((size_t)b * Sn + s) * Hn + n] = hn;
}

// ---------------- launch ----------------
extern "C" void kernel_launch(void* const* d_in, const int* in_sizes, int n_in,
                              void* d_out, int out_size)
{
    const float* batch_H = (const float*)d_in[0];
    const int*   text    = (const int*)  d_in[1];
    const float* Wi      = (const float*)d_in[2];
    const float* Wh      = (const float*)d_in[3];
    const float* bh      = (const float*)d_in[4];
    const float* Ws      = (const float*)d_in[5];
    const float* Wih     = (const float*)d_in[6];
    const float* Whh     = (const float*)d_in[7];
    const float* bih     = (const float*)d_in[8];
    const float* bhh     = (const float*)d_in[9];
    const float* Wg      = (const float*)d_in[10];
    const float* bg      = (const float*)d_in[11];
    float* out = (float*)d_out;

    float *Hp, *ph, *xcat, *gates, *hs, *Wcat;
    cudaGetSymbolAddress((void**)&Hp,    g_Hp);
    cudaGetSymbolAddress((void**)&ph,    g_ph);
    cudaGetSymbolAddress((void**)&xcat,  g_xcat);
    cudaGetSymbolAddress((void**)&gates, g_gates);
    cudaGetSymbolAddress((void**)&hs,    g_hs);
    cudaGetSymbolAddress((void**)&Wcat,  g_Wcat);

    init_state_kernel<<<(Bn * XCn + 255) / 256, 256>>>();
    build_wcat_kernel<<<(4 * Hn * XCn + 255) / 256, 256>>>(Wih, Whh);
    build_ohb_kernel<<<(Cn * 4 * Hn + 255) / 256, 256>>>(Wih, bih, bhh);

    // Hp = batch_H @ Wi^T   [65536 x 512], K=512
    gemm_tf32<false><<<dim3(Hn / 64, (Bn * Tn) / 128), 256>>>(
        batch_H, Dn, Wi, Dn, nullptr, Hp, Hn, Bn * Tn, Hn, Dn);

    for (int s = 0; s < Sn; s++) {
        // ph = h @ Wh^T + bh   (h = xcat[:,512:])
        gemm_tf32<true><<<dim3(Hn / 64, Bn / 128), 256>>>(
            xcat + Dn, XCn, Wh, Hn, bh, ph, Hn, Bn, Hn, Hn);

        attn_kernel<<<Bn, 256>>>(batch_H, Ws);

        // gates = [ctx|h] @ Wcat^T   [1024 x 2048], K=1024
        gemm_tf32<false><<<dim3(4 * Hn / 64, Bn / 128), 256>>>(
            xcat, XCn, Wcat, XCn, nullptr, gates, 4 * Hn, Bn, 4 * Hn, XCn);

        lstm_kernel<<<(Bn * Hn + 255) / 256, 256>>>(text, s);
    }

    // probs = hs @ Wg^T + bg   [21504 x 96]
    sgemm_nt<false, true><<<dim3((Cn + 63) / 64, (Bn * Sn) / 128), 256>>>(
        hs, Hn, Wg, Hn, bg, out, Cn, Bn * Sn, Cn, Hn);
}